// round 2
// baseline (speedup 1.0000x reference)
#include <cuda_runtime.h>
#include <math.h>

#define BB 32
#define DIM 4096
#define NH 32
#define NKV 8
#define GQ 4
#define HD 128
#define KVLEN 4096
#define QKVC 6144          // (NH + 2*NKV) * HD
#define KSPLIT 16          // K-dim split for GEMMs
#define KCH 256            // K chunk per block (DIM / KSPLIT)
#define CHUNK 1024         // KV positions per attention split
#define NSPLIT 4           // KVLEN / CHUNK

// ---------------- scratch (no allocs allowed) ----------------
__device__ float g_part1[KSPLIT][BB][QKVC];     // qkv gemm partials (12.6 MB)
__device__ float g_part2[KSPLIT][BB][DIM];      // out gemm partials (8.4 MB)
__device__ float g_q[BB * NH * HD];             // rope'd q
__device__ float g_knew[BB * NKV * HD];         // rope'd new k
__device__ float g_vnew[BB * NKV * HD];         // new v
__device__ float g_pm[BB * NKV * NSPLIT * GQ];  // partial max
__device__ float g_ps[BB * NKV * NSPLIT * GQ];  // partial sumexp
__device__ float g_pacc[BB * NKV * NSPLIT * GQ * HD]; // partial weighted V
__device__ float g_attn[BB * DIM];              // attention output (pre-wo)

// ---------------- GEMM partial: part[by][b][c] = sum_{d in chunk} x[b][d] * w[d][c]
// x: [BB][DIM], w: [DIM][COLS]. grid (COLS/256, KSPLIT), block 256.
template <int COLS>
__global__ void __launch_bounds__(256) k_gemm_part(const float* __restrict__ x,
                                                   const float* __restrict__ w,
                                                   float* __restrict__ part) {
    __shared__ float xs[KCH][BB];  // transposed x tile, 32 KB
    const int c = blockIdx.x * 256 + threadIdx.x;
    const int d0 = blockIdx.y * KCH;
    for (int i = threadIdx.x; i < KCH * BB; i += 256) {
        int dd = i >> 5, b = i & 31;
        xs[dd][b] = x[b * DIM + d0 + dd];
    }
    __syncthreads();
    float acc[BB];
#pragma unroll
    for (int b = 0; b < BB; b++) acc[b] = 0.f;
    const float* wp = w + (size_t)d0 * COLS + c;
#pragma unroll 4
    for (int dd = 0; dd < KCH; dd++) {
        float wv = wp[(size_t)dd * COLS];
        const float4* xr = (const float4*)xs[dd];
#pragma unroll
        for (int j = 0; j < 8; j++) {
            float4 xv = xr[j];  // broadcast LDS.128
            acc[4 * j + 0] = fmaf(xv.x, wv, acc[4 * j + 0]);
            acc[4 * j + 1] = fmaf(xv.y, wv, acc[4 * j + 1]);
            acc[4 * j + 2] = fmaf(xv.z, wv, acc[4 * j + 2]);
            acc[4 * j + 3] = fmaf(xv.w, wv, acc[4 * j + 3]);
        }
    }
    float* o = part + (size_t)blockIdx.y * BB * COLS + c;
#pragma unroll
    for (int b = 0; b < BB; b++) o[(size_t)b * COLS] = acc[b];
}

// ---------------- reduce qkv partials + rope ----------------
// grid = BB*48 blocks (48 "heads" of 128 cols: 32 q, 8 k, 8 v), block 128.
__global__ void __launch_bounds__(128) k_reduce_rope(const float* __restrict__ rot) {
    const int b = blockIdx.x / 48;
    const int h = blockIdx.x % 48;
    const int t = threadIdx.x;
    float s = 0.f;
#pragma unroll
    for (int p = 0; p < KSPLIT; p++) s += g_part1[p][b][h * HD + t];
    if (h >= 40) {  // v: no rope (uniform per block; safe early return)
        g_vnew[(b * NKV + (h - 40)) * HD + t] = s;
        return;
    }
    __shared__ float vsh[HD];
    vsh[t] = s;
    __syncthreads();
    float o = 0.f;
#pragma unroll 8
    for (int d = 0; d < HD; d++) o = fmaf(vsh[d], rot[d * HD + t], o);
    if (h < 32)
        g_q[(b * NH + h) * HD + t] = o;
    else
        g_knew[(b * NKV + (h - 32)) * HD + t] = o;
}

// ---------------- flash-decode partial attention ----------------
// grid (BB*NKV, NSPLIT), block 256. Position current_pos uses g_knew/g_vnew
// (cache left untouched). Each block: scores -> softmax(chunk) -> p@V partial.
__global__ void __launch_bounds__(256) k_attn_part(const float* __restrict__ ck,
                                                   const float* __restrict__ cv,
                                                   const int* __restrict__ curp) {
    const int bk = blockIdx.x;  // b*NKV + kv
    const int b = bk >> 3, kv = bk & 7;
    const int sp = blockIdx.y;
    const int cur = *curp;
    const int L = cur + 1;
    const int s0 = sp * CHUNK;
    const int scnt = min(CHUNK, L - s0);
    const int pbase = (bk * NSPLIT + sp) * GQ;
    const int t = threadIdx.x;

    if (scnt <= 0) {  // empty split: neutral element for the LSE merge
        if (t < GQ) { g_pm[pbase + t] = -INFINITY; g_ps[pbase + t] = 0.f; }
        for (int i = t; i < GQ * HD; i += 256) g_pacc[pbase * HD + i] = 0.f;
        return;
    }

    __shared__ float sc[GQ][CHUNK];   // 16 KB scores/probs
    __shared__ float4 qsh[GQ][HD / 4];
    __shared__ float red[8];
    __shared__ float mh[GQ], sumh[GQ];

    for (int i = t; i < GQ * HD; i += 256)
        ((float*)qsh)[i] = g_q[(b * NH + kv * GQ) * HD + i];
    __syncthreads();

    const float scale = 0.08838834764831845f;  // 1/sqrt(128)
    // ---- scores: one KV row per thread, float4 streaming ----
    for (int s = t; s < scnt; s += 256) {
        const int sg = s0 + s;
        const float4* kr = (sg == cur)
            ? (const float4*)(g_knew + (b * NKV + kv) * HD)
            : (const float4*)(ck + ((size_t)(b * NKV + kv) * KVLEN + sg) * HD);
        float a0 = 0, a1 = 0, a2 = 0, a3 = 0;
#pragma unroll 8
        for (int j = 0; j < HD / 4; j++) {
            float4 k4 = kr[j];
            float4 q0 = qsh[0][j], q1 = qsh[1][j], q2 = qsh[2][j], q3 = qsh[3][j];
            a0 += k4.x * q0.x + k4.y * q0.y + k4.z * q0.z + k4.w * q0.w;
            a1 += k4.x * q1.x + k4.y * q1.y + k4.z * q1.z + k4.w * q1.w;
            a2 += k4.x * q2.x + k4.y * q2.y + k4.z * q2.z + k4.w * q2.w;
            a3 += k4.x * q3.x + k4.y * q3.y + k4.z * q3.z + k4.w * q3.w;
        }
        sc[0][s] = a0 * scale; sc[1][s] = a1 * scale;
        sc[2][s] = a2 * scale; sc[3][s] = a3 * scale;
    }
    __syncthreads();

    // ---- per-chunk softmax (max, exp, sum) ----
    const int lane = t & 31, wid = t >> 5;
    for (int h = 0; h < GQ; h++) {
        float lm = -INFINITY;
        for (int s = t; s < scnt; s += 256) lm = fmaxf(lm, sc[h][s]);
#pragma unroll
        for (int o = 16; o > 0; o >>= 1) lm = fmaxf(lm, __shfl_xor_sync(0xffffffffu, lm, o));
        if (lane == 0) red[wid] = lm;
        __syncthreads();
        if (t == 0) {
            float m = red[0];
            for (int wj = 1; wj < 8; wj++) m = fmaxf(m, red[wj]);
            mh[h] = m;
        }
        __syncthreads();
        const float m = mh[h];
        float ls = 0.f;
        for (int s = t; s < scnt; s += 256) {
            float p = __expf(sc[h][s] - m);
            sc[h][s] = p;
            ls += p;
        }
#pragma unroll
        for (int o = 16; o > 0; o >>= 1) ls += __shfl_xor_sync(0xffffffffu, ls, o);
        if (lane == 0) red[wid] = ls;
        __syncthreads();
        if (t == 0) {
            float ssum = 0.f;
            for (int wj = 0; wj < 8; wj++) ssum += red[wj];
            sumh[h] = ssum;
        }
        __syncthreads();
    }

    // ---- p @ V: one dim per thread (coalesced), 4 heads per thread ----
    if (t < HD) {
        const int d = t;
        float a0 = 0, a1 = 0, a2 = 0, a3 = 0;
        const float* vbase = cv + ((size_t)(b * NKV + kv) * KVLEN + s0) * HD + d;
        const float vnew = g_vnew[(b * NKV + kv) * HD + d];
#pragma unroll 4
        for (int s = 0; s < scnt; s++) {
            const int sg = s0 + s;
            float vv = (sg == cur) ? vnew : vbase[(size_t)s * HD];
            a0 = fmaf(sc[0][s], vv, a0);
            a1 = fmaf(sc[1][s], vv, a1);
            a2 = fmaf(sc[2][s], vv, a2);
            a3 = fmaf(sc[3][s], vv, a3);
        }
        g_pacc[(pbase + 0) * HD + d] = a0;
        g_pacc[(pbase + 1) * HD + d] = a1;
        g_pacc[(pbase + 2) * HD + d] = a2;
        g_pacc[(pbase + 3) * HD + d] = a3;
    }
    if (t >= 128 && t < 128 + GQ) {
        g_pm[pbase + (t - 128)] = mh[t - 128];
        g_ps[pbase + (t - 128)] = sumh[t - 128];
    }
}

// ---------------- LSE merge across splits ----------------
__global__ void __launch_bounds__(128) k_combine() {
    const int bk = blockIdx.x;
    const int b = bk >> 3, kv = bk & 7;
    const int d = threadIdx.x;
    for (int h = 0; h < GQ; h++) {
        float m = -INFINITY;
#pragma unroll
        for (int sp = 0; sp < NSPLIT; sp++)
            m = fmaxf(m, g_pm[(bk * NSPLIT + sp) * GQ + h]);
        float den = 0.f, num = 0.f;
#pragma unroll
        for (int sp = 0; sp < NSPLIT; sp++) {
            float e = __expf(g_pm[(bk * NSPLIT + sp) * GQ + h] - m);
            den += g_ps[(bk * NSPLIT + sp) * GQ + h] * e;
            num += g_pacc[((bk * NSPLIT + sp) * GQ + h) * HD + d] * e;
        }
        g_attn[(b * NH + kv * GQ + h) * HD + d] = num / den;
    }
}

// ---------------- final reduce of out-gemm partials ----------------
__global__ void __launch_bounds__(256) k_out_reduce(float* __restrict__ out) {
    const int i = blockIdx.x * 256 + threadIdx.x;  // grid sized exactly
    const float* p2 = (const float*)g_part2;
    float s = 0.f;
#pragma unroll
    for (int p = 0; p < KSPLIT; p++) s += p2[(size_t)p * BB * DIM + i];
    out[i] = s;
}

extern "C" void kernel_launch(void* const* d_in, const int* in_sizes, int n_in,
                              void* d_out, int out_size) {
    const float* x    = (const float*)d_in[0];  // attn_norm (1,1,32,4096)
    const float* wqkv = (const float*)d_in[1];  // (4096, 6144)
    const float* wo   = (const float*)d_in[2];  // (4096, 4096)
    const float* rot  = (const float*)d_in[3];  // (128, 128)
    const float* ck   = (const float*)d_in[4];  // (32,8,4096,128)
    const float* cv   = (const float*)d_in[5];  // (32,8,4096,128)
    const int*   curp = (const int*)d_in[6];    // current_pos (low 32 bits)
    float* out = (float*)d_out;

    void *p1, *p2, *attnp;
    cudaGetSymbolAddress(&p1, g_part1);
    cudaGetSymbolAddress(&p2, g_part2);
    cudaGetSymbolAddress(&attnp, g_attn);

    k_gemm_part<QKVC><<<dim3(QKVC / 256, KSPLIT), 256>>>(x, wqkv, (float*)p1);
    k_reduce_rope<<<BB * 48, 128>>>(rot);
    k_attn_part<<<dim3(BB * NKV, NSPLIT), 256>>>(ck, cv, curp);
    k_combine<<<BB * NKV, 128>>>();
    k_gemm_part<DIM><<<dim3(DIM / 256, KSPLIT), 256>>>((const float*)attnp, wo, (float*)p2);
    k_out_reduce<<<BB * DIM / 256, 256>>>(out);
}

// round 3
// speedup vs baseline: 1.2573x; 1.2573x over previous
#include <cuda_runtime.h>
#include <math.h>

#define BB 32
#define DIM 4096
#define NH 32
#define NKV 8
#define GQ 4
#define HD 128
#define KVLEN 4096
#define QKVC 6144          // (NH + 2*NKV) * HD
#define KSPLIT 16          // K-dim split for GEMMs
#define KCH 256            // K chunk per block (DIM / KSPLIT)
#define CHUNK 512          // KV positions per attention split
#define NSPLIT 8           // KVLEN / CHUNK

// packed fp32x2 FMA (sm_100+): 2x FLOP per issue slot vs FFMA
#define FMA_F32X2(d, a, b, c) \
    asm("fma.rn.f32x2 %0, %1, %2, %3;" : "=l"(d) : "l"(a), "l"(b), "l"(c))

// ---------------- scratch (no allocs allowed) ----------------
__device__ float g_part1[KSPLIT][BB][QKVC];     // qkv gemm partials
__device__ float g_part2[KSPLIT][BB][DIM];      // out gemm partials
__device__ float g_q[BB * NH * HD];             // rope'd q
__device__ float g_knew[BB * NKV * HD];         // rope'd new k
__device__ float g_vnew[BB * NKV * HD];         // new v
__device__ float g_pm[BB * NKV * NSPLIT * GQ];  // partial max
__device__ float g_ps[BB * NKV * NSPLIT * GQ];  // partial sumexp
__device__ float g_pacc[BB * NKV * NSPLIT * GQ * HD]; // partial weighted V
__device__ float g_attn[BB * DIM];              // attention output (pre-wo)

// ---------------- GEMM partial with packed f32x2 FMA ----------------
// part[by][b][c] = sum_{d in chunk} x[b][d]*w[d][c]. grid (COLS/256, KSPLIT).
template <int COLS>
__global__ void __launch_bounds__(256) k_gemm_part(const float* __restrict__ x,
                                                   const float* __restrict__ w,
                                                   float* __restrict__ part) {
    __shared__ float xs[KCH][BB];  // transposed x tile, 32 KB (rows 128B-aligned)
    const int c = blockIdx.x * 256 + threadIdx.x;
    const int d0 = blockIdx.y * KCH;
    for (int i = threadIdx.x; i < KCH * BB; i += 256) {
        int dd = i >> 5, b = i & 31;
        xs[dd][b] = x[b * DIM + d0 + dd];
    }
    __syncthreads();
    unsigned long long acc[16];  // 16 f32x2 pairs = 32 batch accumulators
#pragma unroll
    for (int i = 0; i < 16; i++) acc[i] = 0ull;
    const float* wp = w + (size_t)d0 * COLS + c;
    float wv = wp[0];
#pragma unroll 4
    for (int dd = 0; dd < KCH; dd++) {
        float wnext = (dd + 1 < KCH) ? wp[(size_t)(dd + 1) * COLS] : 0.f;
        unsigned long long w2;
        asm("mov.b64 %0, {%1, %1};" : "=l"(w2) : "f"(wv));
        const ulonglong2* xr = (const ulonglong2*)xs[dd];
#pragma unroll
        for (int j = 0; j < 8; j++) {
            ulonglong2 xv = xr[j];  // LDS.128 broadcast: 4 batches
            FMA_F32X2(acc[2 * j + 0], xv.x, w2, acc[2 * j + 0]);
            FMA_F32X2(acc[2 * j + 1], xv.y, w2, acc[2 * j + 1]);
        }
        wv = wnext;
    }
    float* o = part + (size_t)blockIdx.y * BB * COLS + c;
#pragma unroll
    for (int i = 0; i < 16; i++) {
        float lo, hi;
        asm("mov.b64 {%0, %1}, %2;" : "=f"(lo), "=f"(hi) : "l"(acc[i]));
        o[(size_t)(2 * i) * COLS] = lo;
        o[(size_t)(2 * i + 1) * COLS] = hi;
    }
}

// ---------------- reduce qkv partials + rope ----------------
__global__ void __launch_bounds__(128) k_reduce_rope(const float* __restrict__ rot) {
    const int b = blockIdx.x / 48;
    const int h = blockIdx.x % 48;
    const int t = threadIdx.x;
    float s = 0.f;
#pragma unroll
    for (int p = 0; p < KSPLIT; p++) s += g_part1[p][b][h * HD + t];
    if (h >= 40) {  // v: no rope (uniform per block)
        g_vnew[(b * NKV + (h - 40)) * HD + t] = s;
        return;
    }
    __shared__ float vsh[HD];
    vsh[t] = s;
    __syncthreads();
    float o = 0.f;
#pragma unroll 8
    for (int d = 0; d < HD; d++) o = fmaf(vsh[d], rot[d * HD + t], o);
    if (h < 32)
        g_q[(b * NH + h) * HD + t] = o;
    else
        g_knew[(b * NKV + (h - 32)) * HD + t] = o;
}

// ---------------- flash-decode partial attention ----------------
// grid (BB*NKV, NSPLIT), block 256.
__global__ void __launch_bounds__(256) k_attn_part(const float* __restrict__ ck,
                                                   const float* __restrict__ cv,
                                                   const int* __restrict__ curp) {
    const int bk = blockIdx.x;  // b*NKV + kv
    const int b = bk >> 3, kv = bk & 7;
    const int sp = blockIdx.y;
    const int cur = *curp;
    const int L = cur + 1;
    const int s0 = sp * CHUNK;
    const int scnt = min(CHUNK, L - s0);
    const int pbase = (bk * NSPLIT + sp) * GQ;
    const int t = threadIdx.x;

    if (scnt <= 0) {  // empty split: neutral for the LSE merge
        if (t < GQ) { g_pm[pbase + t] = -INFINITY; g_ps[pbase + t] = 0.f; }
        for (int i = t; i < GQ * HD; i += 256) g_pacc[pbase * HD + i] = 0.f;
        return;
    }
    const bool has_cur = (s0 + CHUNK >= L);  // last nonempty split holds cur at s=scnt-1

    __shared__ float sc[GQ][CHUNK];   // 8 KB scores/probs
    __shared__ float4 qsh[GQ][HD / 4];
    __shared__ float red[8];
    __shared__ float mh[GQ], sumh[GQ];
    __shared__ float vred[GQ][HD];    // V-stage cross-half reduce

    for (int i = t; i < GQ * HD; i += 256)
        ((float*)qsh)[i] = g_q[(b * NH + kv * GQ) * HD + i];
    __syncthreads();

    const float scale = 0.08838834764831845f;  // 1/sqrt(128)
    // ---- scores: one KV row per thread, float4 streaming ----
    for (int s = t; s < scnt; s += 256) {
        const float4* kr = (has_cur && s == scnt - 1)
            ? (const float4*)(g_knew + (b * NKV + kv) * HD)
            : (const float4*)(ck + ((size_t)(b * NKV + kv) * KVLEN + s0 + s) * HD);
        float a0 = 0, a1 = 0, a2 = 0, a3 = 0;
#pragma unroll 8
        for (int j = 0; j < HD / 4; j++) {
            float4 k4 = kr[j];
            float4 q0 = qsh[0][j], q1 = qsh[1][j], q2 = qsh[2][j], q3 = qsh[3][j];
            a0 += k4.x * q0.x + k4.y * q0.y + k4.z * q0.z + k4.w * q0.w;
            a1 += k4.x * q1.x + k4.y * q1.y + k4.z * q1.z + k4.w * q1.w;
            a2 += k4.x * q2.x + k4.y * q2.y + k4.z * q2.z + k4.w * q2.w;
            a3 += k4.x * q3.x + k4.y * q3.y + k4.z * q3.z + k4.w * q3.w;
        }
        sc[0][s] = a0 * scale; sc[1][s] = a1 * scale;
        sc[2][s] = a2 * scale; sc[3][s] = a3 * scale;
    }
    __syncthreads();

    // ---- softmax, all 4 heads in parallel: 64 threads per head ----
    {
        const int h = t >> 6, l64 = t & 63, wid = t >> 5, lane = t & 31;
        float lm = -INFINITY;
        for (int s = l64; s < scnt; s += 64) lm = fmaxf(lm, sc[h][s]);
#pragma unroll
        for (int o = 16; o > 0; o >>= 1) lm = fmaxf(lm, __shfl_xor_sync(0xffffffffu, lm, o));
        if (lane == 0) red[wid] = lm;
        __syncthreads();
        if (l64 == 0) mh[h] = fmaxf(red[2 * h], red[2 * h + 1]);
        __syncthreads();
        const float m = mh[h];
        float ls = 0.f;
        for (int s = l64; s < scnt; s += 64) {
            float p = __expf(sc[h][s] - m);
            sc[h][s] = p;
            ls += p;
        }
#pragma unroll
        for (int o = 16; o > 0; o >>= 1) ls += __shfl_xor_sync(0xffffffffu, ls, o);
        if (lane == 0) red[wid] = ls;
        __syncthreads();
        if (l64 == 0) sumh[h] = red[2 * h] + red[2 * h + 1];
    }
    __syncthreads();

    // ---- p @ V: all 256 threads. d = t&127, s split by 2 halves ----
    {
        const int d = t & 127, half = t >> 7;
        float a0 = 0, a1 = 0, a2 = 0, a3 = 0;
        const float* vbase = cv + ((size_t)(b * NKV + kv) * KVLEN + s0) * HD + d;
        const int slim = scnt - (has_cur ? 1 : 0);
#pragma unroll 4
        for (int s = half; s < slim; s += 2) {
            float vv = vbase[(size_t)s * HD];
            a0 = fmaf(sc[0][s], vv, a0);
            a1 = fmaf(sc[1][s], vv, a1);
            a2 = fmaf(sc[2][s], vv, a2);
            a3 = fmaf(sc[3][s], vv, a3);
        }
        if (has_cur && ((scnt - 1) & 1) == half) {
            const int s = scnt - 1;
            float vv = g_vnew[(b * NKV + kv) * HD + d];
            a0 = fmaf(sc[0][s], vv, a0);
            a1 = fmaf(sc[1][s], vv, a1);
            a2 = fmaf(sc[2][s], vv, a2);
            a3 = fmaf(sc[3][s], vv, a3);
        }
        if (half == 1) {
            vred[0][d] = a0; vred[1][d] = a1; vred[2][d] = a2; vred[3][d] = a3;
        }
        __syncthreads();
        if (half == 0) {
            g_pacc[(pbase + 0) * HD + d] = a0 + vred[0][d];
            g_pacc[(pbase + 1) * HD + d] = a1 + vred[1][d];
            g_pacc[(pbase + 2) * HD + d] = a2 + vred[2][d];
            g_pacc[(pbase + 3) * HD + d] = a3 + vred[3][d];
        }
        if (t < GQ) {
            g_pm[pbase + t] = mh[t];
            g_ps[pbase + t] = sumh[t];
        }
    }
}

// ---------------- LSE merge across splits ----------------
__global__ void __launch_bounds__(128) k_combine() {
    const int bk = blockIdx.x;
    const int b = bk >> 3, kv = bk & 7;
    const int d = threadIdx.x;
    for (int h = 0; h < GQ; h++) {
        float m = -INFINITY;
#pragma unroll
        for (int sp = 0; sp < NSPLIT; sp++)
            m = fmaxf(m, g_pm[(bk * NSPLIT + sp) * GQ + h]);
        float den = 0.f, num = 0.f;
#pragma unroll
        for (int sp = 0; sp < NSPLIT; sp++) {
            float e = __expf(g_pm[(bk * NSPLIT + sp) * GQ + h] - m);
            den += g_ps[(bk * NSPLIT + sp) * GQ + h] * e;
            num += g_pacc[((bk * NSPLIT + sp) * GQ + h) * HD + d] * e;
        }
        g_attn[(b * NH + kv * GQ + h) * HD + d] = num / den;
    }
}

// ---------------- final reduce of out-gemm partials ----------------
__global__ void __launch_bounds__(256) k_out_reduce(float* __restrict__ out) {
    const int i = blockIdx.x * 256 + threadIdx.x;
    const float* p2 = (const float*)g_part2;
    float s = 0.f;
#pragma unroll
    for (int p = 0; p < KSPLIT; p++) s += p2[(size_t)p * BB * DIM + i];
    out[i] = s;
}

extern "C" void kernel_launch(void* const* d_in, const int* in_sizes, int n_in,
                              void* d_out, int out_size) {
    const float* x    = (const float*)d_in[0];  // attn_norm (1,1,32,4096)
    const float* wqkv = (const float*)d_in[1];  // (4096, 6144)
    const float* wo   = (const float*)d_in[2];  // (4096, 4096)
    const float* rot  = (const float*)d_in[3];  // (128, 128)
    const float* ck   = (const float*)d_in[4];  // (32,8,4096,128)
    const float* cv   = (const float*)d_in[5];  // (32,8,4096,128)
    const int*   curp = (const int*)d_in[6];    // current_pos (low 32 bits)
    float* out = (float*)d_out;

    void *p1, *p2, *attnp;
    cudaGetSymbolAddress(&p1, g_part1);
    cudaGetSymbolAddress(&p2, g_part2);
    cudaGetSymbolAddress(&attnp, g_attn);

    k_gemm_part<QKVC><<<dim3(QKVC / 256, KSPLIT), 256>>>(x, wqkv, (float*)p1);
    k_reduce_rope<<<BB * 48, 128>>>(rot);
    k_attn_part<<<dim3(BB * NKV, NSPLIT), 256>>>(ck, cv, curp);
    k_combine<<<BB * NKV, 128>>>();
    k_gemm_part<DIM><<<dim3(DIM / 256, KSPLIT), 256>>>((const float*)attnp, wo, (float*)p2);
    k_out_reduce<<<BB * DIM / 256, 256>>>(out);
}

// round 4
// speedup vs baseline: 1.4052x; 1.1176x over previous
#include <cuda_runtime.h>
#include <math.h>

#define BB 32
#define DIM 4096
#define NH 32
#define NKV 8
#define GQ 4
#define HD 128
#define KVLEN 4096
#define QKVC 6144          // (NH + 2*NKV) * HD
#define KSPLIT 16          // K-dim split for GEMMs
#define KCH 256            // K chunk per block (DIM / KSPLIT)
#define CHUNK 256          // KV positions per attention split
#define NSPLIT 16          // KVLEN / CHUNK

// packed fp32x2 FMA (sm_100+): 2x FLOP per issue slot vs FFMA
#define FMA_F32X2(d, a, b, c) \
    asm("fma.rn.f32x2 %0, %1, %2, %3;" : "=l"(d) : "l"(a), "l"(b), "l"(c))

// ---------------- scratch (no allocs allowed) ----------------
__device__ float g_part1[KSPLIT][BB][QKVC];     // qkv gemm partials
__device__ float g_part2[KSPLIT][BB][DIM];      // out gemm partials
__device__ float g_q[BB * NH * HD];             // rope'd q
__device__ float g_knew[BB * NKV * HD];         // rope'd new k
__device__ float g_vnew[BB * NKV * HD];         // new v
__device__ float g_pm[BB * NKV * NSPLIT * GQ];  // partial max
__device__ float g_ps[BB * NKV * NSPLIT * GQ];  // partial sumexp
__device__ float g_pacc[BB * NKV * NSPLIT * GQ * HD]; // partial weighted V
__device__ float g_attn[BB * DIM];              // attention output (pre-wo)

// ---------------- GEMM partial: f32x2 FMA + depth-8 weight prefetch ----------------
// part[by][b][c] = sum_{d in chunk} x[b][d]*w[d][c]. grid (COLS/256, KSPLIT).
template <int COLS>
__global__ void __launch_bounds__(256) k_gemm_part(const float* __restrict__ x,
                                                   const float* __restrict__ w,
                                                   float* __restrict__ part) {
    __shared__ float xs[KCH][BB];  // transposed x tile, 32 KB
    const int c = blockIdx.x * 256 + threadIdx.x;
    const int d0 = blockIdx.y * KCH;
    for (int i = threadIdx.x; i < KCH * BB; i += 256) {
        int dd = i >> 5, b = i & 31;
        xs[dd][b] = x[b * DIM + d0 + dd];
    }
    __syncthreads();
    unsigned long long acc[16];  // 16 f32x2 pairs = 32 batch accumulators
#pragma unroll
    for (int i = 0; i < 16; i++) acc[i] = 0ull;

    const float* wcol = w + (size_t)d0 * COLS + c;
    float wv[8];
#pragma unroll
    for (int u = 0; u < 8; u++) wv[u] = wcol[(size_t)u * COLS];  // MLP=8 prime

    for (int g = 0; g < KCH; g += 8) {
        float wn[8];
        if (g + 8 < KCH) {
            const float* wnp = wcol + (size_t)(g + 8) * COLS;
#pragma unroll
            for (int u = 0; u < 8; u++) wn[u] = wnp[(size_t)u * COLS];  // 8 in flight
        } else {
#pragma unroll
            for (int u = 0; u < 8; u++) wn[u] = 0.f;
        }
#pragma unroll
        for (int u = 0; u < 8; u++) {
            unsigned long long w2;
            asm("mov.b64 %0, {%1, %1};" : "=l"(w2) : "f"(wv[u]));
            const ulonglong2* xr = (const ulonglong2*)xs[g + u];
#pragma unroll
            for (int j = 0; j < 8; j++) {
                ulonglong2 xv = xr[j];  // LDS.128 broadcast: 4 batches
                FMA_F32X2(acc[2 * j + 0], xv.x, w2, acc[2 * j + 0]);
                FMA_F32X2(acc[2 * j + 1], xv.y, w2, acc[2 * j + 1]);
            }
        }
#pragma unroll
        for (int u = 0; u < 8; u++) wv[u] = wn[u];
    }

    float* o = part + (size_t)blockIdx.y * BB * COLS + c;
#pragma unroll
    for (int i = 0; i < 16; i++) {
        float lo, hi;
        asm("mov.b64 {%0, %1}, %2;" : "=f"(lo), "=f"(hi) : "l"(acc[i]));
        o[(size_t)(2 * i) * COLS] = lo;
        o[(size_t)(2 * i + 1) * COLS] = hi;
    }
}

// ---------------- reduce qkv partials + rope ----------------
__global__ void __launch_bounds__(128) k_reduce_rope(const float* __restrict__ rot) {
    const int b = blockIdx.x / 48;
    const int h = blockIdx.x % 48;
    const int t = threadIdx.x;
    float s = 0.f;
#pragma unroll
    for (int p = 0; p < KSPLIT; p++) s += g_part1[p][b][h * HD + t];
    if (h >= 40) {  // v: no rope (uniform per block)
        g_vnew[(b * NKV + (h - 40)) * HD + t] = s;
        return;
    }
    __shared__ float vsh[HD];
    vsh[t] = s;
    __syncthreads();
    float o = 0.f;
#pragma unroll 8
    for (int d = 0; d < HD; d++) o = fmaf(vsh[d], rot[d * HD + t], o);
    if (h < 32)
        g_q[(b * NH + h) * HD + t] = o;
    else
        g_knew[(b * NKV + (h - 32)) * HD + t] = o;
}

// ---------------- flash-decode partial attention ----------------
// grid (BB*NKV, NSPLIT), block 256. Splits beyond L exit with NO writes
// (combine is length-aware and never reads them).
__global__ void __launch_bounds__(256) k_attn_part(const float* __restrict__ ck,
                                                   const float* __restrict__ cv,
                                                   const int* __restrict__ curp) {
    const int bk = blockIdx.x;  // b*NKV + kv
    const int b = bk >> 3, kv = bk & 7;
    const int sp = blockIdx.y;
    const int cur = *curp;
    const int L = cur + 1;
    const int s0 = sp * CHUNK;
    const int scnt = min(CHUNK, L - s0);
    if (scnt <= 0) return;
    const int pbase = (bk * NSPLIT + sp) * GQ;
    const int t = threadIdx.x;
    const bool has_cur = (s0 + CHUNK >= L);  // cur lives at s = scnt-1 of last split

    __shared__ float4 sc4[CHUNK];     // transposed probs: sc4[s] = {h0,h1,h2,h3}
    __shared__ float4 qsh[GQ][HD / 4];
    __shared__ float red[8];
    __shared__ float mh[GQ], sumh[GQ];
    __shared__ float vred[GQ][HD];    // V-stage cross-half reduce

    for (int i = t; i < GQ * HD; i += 256)
        ((float*)qsh)[i] = g_q[(b * NH + kv * GQ) * HD + i];
    __syncthreads();

    const float scale = 0.08838834764831845f;  // 1/sqrt(128)
    // ---- scores: one KV row per thread ----
    if (t < scnt) {
        const int s = t;
        const float4* kr = (has_cur && s == scnt - 1)
            ? (const float4*)(g_knew + (b * NKV + kv) * HD)
            : (const float4*)(ck + ((size_t)(b * NKV + kv) * KVLEN + s0 + s) * HD);
        float a0 = 0, a1 = 0, a2 = 0, a3 = 0;
#pragma unroll 8
        for (int j = 0; j < HD / 4; j++) {
            float4 k4 = kr[j];
            float4 q0 = qsh[0][j], q1 = qsh[1][j], q2 = qsh[2][j], q3 = qsh[3][j];
            a0 += k4.x * q0.x + k4.y * q0.y + k4.z * q0.z + k4.w * q0.w;
            a1 += k4.x * q1.x + k4.y * q1.y + k4.z * q1.z + k4.w * q1.w;
            a2 += k4.x * q2.x + k4.y * q2.y + k4.z * q2.z + k4.w * q2.w;
            a3 += k4.x * q3.x + k4.y * q3.y + k4.z * q3.z + k4.w * q3.w;
        }
        sc4[s] = make_float4(a0 * scale, a1 * scale, a2 * scale, a3 * scale);
    }
    __syncthreads();

    // ---- softmax, 4 heads in parallel: 64 threads per head ----
    {
        const int h = t >> 6, l64 = t & 63, wid = t >> 5, lane = t & 31;
        const float* schf = (const float*)sc4;  // schf[s*4 + h]
        float lm = -INFINITY;
        for (int s = l64; s < scnt; s += 64) lm = fmaxf(lm, schf[s * 4 + h]);
#pragma unroll
        for (int o = 16; o > 0; o >>= 1) lm = fmaxf(lm, __shfl_xor_sync(0xffffffffu, lm, o));
        if (lane == 0) red[wid] = lm;
        __syncthreads();
        if (l64 == 0) mh[h] = fmaxf(red[2 * h], red[2 * h + 1]);
        __syncthreads();
        const float m = mh[h];
        float ls = 0.f;
        float* scw = (float*)sc4;
        for (int s = l64; s < scnt; s += 64) {
            float p = __expf(scw[s * 4 + h] - m);
            scw[s * 4 + h] = p;
            ls += p;
        }
#pragma unroll
        for (int o = 16; o > 0; o >>= 1) ls += __shfl_xor_sync(0xffffffffu, ls, o);
        if (lane == 0) red[wid] = ls;
        __syncthreads();
        if (l64 == 0) sumh[h] = red[2 * h] + red[2 * h + 1];
    }
    __syncthreads();

    // ---- p @ V: 256 threads, d = t&127, s split over 2 halves; f32x2 FMA ----
    {
        const int d = t & 127, half = t >> 7;
        unsigned long long a01 = 0ull, a23 = 0ull;
        const float* vbase = cv + ((size_t)(b * NKV + kv) * KVLEN + s0) * HD + d;
        const int slim = scnt - (has_cur ? 1 : 0);
#pragma unroll 4
        for (int s = half; s < slim; s += 2) {
            float vv = vbase[(size_t)s * HD];
            unsigned long long v2, p01, p23;
            float4 p = sc4[s];  // broadcast LDS.128
            asm("mov.b64 %0, {%1, %1};" : "=l"(v2) : "f"(vv));
            asm("mov.b64 %0, {%1, %2};" : "=l"(p01) : "f"(p.x), "f"(p.y));
            asm("mov.b64 %0, {%1, %2};" : "=l"(p23) : "f"(p.z), "f"(p.w));
            FMA_F32X2(a01, p01, v2, a01);
            FMA_F32X2(a23, p23, v2, a23);
        }
        if (has_cur && ((scnt - 1) & 1) == half) {
            const int s = scnt - 1;
            float vv = g_vnew[(b * NKV + kv) * HD + d];
            unsigned long long v2, p01, p23;
            float4 p = sc4[s];
            asm("mov.b64 %0, {%1, %1};" : "=l"(v2) : "f"(vv));
            asm("mov.b64 %0, {%1, %2};" : "=l"(p01) : "f"(p.x), "f"(p.y));
            asm("mov.b64 %0, {%1, %2};" : "=l"(p23) : "f"(p.z), "f"(p.w));
            FMA_F32X2(a01, p01, v2, a01);
            FMA_F32X2(a23, p23, v2, a23);
        }
        float a0, a1, a2, a3;
        asm("mov.b64 {%0, %1}, %2;" : "=f"(a0), "=f"(a1) : "l"(a01));
        asm("mov.b64 {%0, %1}, %2;" : "=f"(a2), "=f"(a3) : "l"(a23));
        if (half == 1) {
            vred[0][d] = a0; vred[1][d] = a1; vred[2][d] = a2; vred[3][d] = a3;
        }
        __syncthreads();
        if (half == 0) {
            g_pacc[(pbase + 0) * HD + d] = a0 + vred[0][d];
            g_pacc[(pbase + 1) * HD + d] = a1 + vred[1][d];
            g_pacc[(pbase + 2) * HD + d] = a2 + vred[2][d];
            g_pacc[(pbase + 3) * HD + d] = a3 + vred[3][d];
        }
        if (t < GQ) {
            g_pm[pbase + t] = mh[t];
            g_ps[pbase + t] = sumh[t];
        }
    }
}

// ---------------- LSE merge across splits (length-aware) ----------------
// grid (BB*NKV, GQ), block 128.
__global__ void __launch_bounds__(128) k_combine(const int* __restrict__ curp) {
    const int bk = blockIdx.x;
    const int b = bk >> 3, kv = bk & 7;
    const int h = blockIdx.y;
    const int d = threadIdx.x;
    const int nsp = (*curp + CHUNK) / CHUNK;  // ceil(L/CHUNK)

    __shared__ float esh[NSPLIT];
    __shared__ float dens;
    if (d == 0) {
        float m = -INFINITY;
        for (int sp = 0; sp < nsp; sp++)
            m = fmaxf(m, g_pm[(bk * NSPLIT + sp) * GQ + h]);
        float den = 0.f;
        for (int sp = 0; sp < nsp; sp++) {
            float e = __expf(g_pm[(bk * NSPLIT + sp) * GQ + h] - m);
            esh[sp] = e;
            den += g_ps[(bk * NSPLIT + sp) * GQ + h] * e;
        }
        dens = den;
    }
    __syncthreads();
    float num = 0.f;
#pragma unroll 4
    for (int sp = 0; sp < nsp; sp++)
        num = fmaf(g_pacc[((bk * NSPLIT + sp) * GQ + h) * HD + d], esh[sp], num);
    g_attn[(b * NH + kv * GQ + h) * HD + d] = num / dens;
}

// ---------------- final reduce of out-gemm partials ----------------
__global__ void __launch_bounds__(256) k_out_reduce(float* __restrict__ out) {
    const int i = blockIdx.x * 256 + threadIdx.x;
    const float* p2 = (const float*)g_part2;
    float s = 0.f;
#pragma unroll
    for (int p = 0; p < KSPLIT; p++) s += p2[(size_t)p * BB * DIM + i];
    out[i] = s;
}

extern "C" void kernel_launch(void* const* d_in, const int* in_sizes, int n_in,
                              void* d_out, int out_size) {
    const float* x    = (const float*)d_in[0];  // attn_norm (1,1,32,4096)
    const float* wqkv = (const float*)d_in[1];  // (4096, 6144)
    const float* wo   = (const float*)d_in[2];  // (4096, 4096)
    const float* rot  = (const float*)d_in[3];  // (128, 128)
    const float* ck   = (const float*)d_in[4];  // (32,8,4096,128)
    const float* cv   = (const float*)d_in[5];  // (32,8,4096,128)
    const int*   curp = (const int*)d_in[6];    // current_pos (low 32 bits)
    float* out = (float*)d_out;

    void *p1, *p2, *attnp;
    cudaGetSymbolAddress(&p1, g_part1);
    cudaGetSymbolAddress(&p2, g_part2);
    cudaGetSymbolAddress(&attnp, g_attn);

    k_gemm_part<QKVC><<<dim3(QKVC / 256, KSPLIT), 256>>>(x, wqkv, (float*)p1);
    k_reduce_rope<<<BB * 48, 128>>>(rot);
    k_attn_part<<<dim3(BB * NKV, NSPLIT), 256>>>(ck, cv, curp);
    k_combine<<<dim3(BB * NKV, GQ), 128>>>(curp);
    k_gemm_part<DIM><<<dim3(DIM / 256, KSPLIT), 256>>>((const float*)attnp, wo, (float*)p2);
    k_out_reduce<<<BB * DIM / 256, 256>>>(out);
}